// round 7
// baseline (speedup 1.0000x reference)
#include <cuda_runtime.h>
#include <math.h>
#include <stdint.h>

#define B_    2
#define N_    1024
#define D_    1024
#define H_    16
#define DH_   64
#define MLP_  4096
#define DEPTH_ 6
#define M_    (B_ * N_)   /* 2048 rows */

// ---------------- scratch -----------------------------------------------
__device__ float g_h   [(size_t)M_ * D_];          // permuted (GEMM A)
__device__ float g_qkv [(size_t)M_ * 3 * D_];      // natural
__device__ float g_attn[(size_t)B_ * H_ * N_ * N_];
__device__ float g_o   [(size_t)M_ * D_];          // permuted (GEMM A)
__device__ float g_mlp [(size_t)M_ * MLP_];        // permuted (GEMM A)
// transposed + tf32-rounded + k-permuted weights: [N][Kperm] per layer
__device__ float g_wqkv[(size_t)DEPTH_ * D_ * 3 * D_];
__device__ float g_wout[(size_t)DEPTH_ * D_ * D_];
__device__ float g_w1  [(size_t)DEPTH_ * D_ * MLP_];
__device__ float g_w2  [(size_t)DEPTH_ * MLP_ * D_];

// ---------------- helpers ---------------------------------------------------
__device__ __forceinline__ float f2tf(float x) {
    uint32_t u; asm("cvt.rna.tf32.f32 %0, %1;" : "=r"(u) : "f"(x));
    return __uint_as_float(u);
}
// k-permutation within 32-float blocks: w=c&31 -> 8*(w&3) + (w>>2)
__device__ __forceinline__ int permc(int c) {
    return (c & ~31) | (((c & 3) << 3) | ((c >> 2) & 7));
}
__device__ __forceinline__ void mma8(float* d, const float* a, const float* b) {
    asm volatile(
        "mma.sync.aligned.m16n8k8.row.col.f32.tf32.tf32.f32 "
        "{%0,%1,%2,%3},{%4,%5,%6,%7},{%8,%9},{%0,%1,%2,%3};"
        : "+f"(d[0]), "+f"(d[1]), "+f"(d[2]), "+f"(d[3])
        : "r"(__float_as_uint(a[0])), "r"(__float_as_uint(a[1])),
          "r"(__float_as_uint(a[2])), "r"(__float_as_uint(a[3])),
          "r"(__float_as_uint(b[0])), "r"(__float_as_uint(b[1])));
}
__device__ __forceinline__ void cp16(void* smem_dst, const void* gmem_src) {
    uint32_t dst = (uint32_t)__cvta_generic_to_shared(smem_dst);
    asm volatile("cp.async.cg.shared.global [%0], [%1], 16;"
                 :: "r"(dst), "l"(gmem_src));
}
__device__ __forceinline__ void cp_commit() {
    asm volatile("cp.async.commit_group;");
}

// ---------------- weight pre-pass: [K,N] -> [N, Kperm], tf32-rounded --------
__global__ void __launch_bounds__(256) wtrans_kernel(
    const float* __restrict__ src, float* __restrict__ dst, int K, int N)
{
    __shared__ float t[32][33];
    int n0 = blockIdx.x * 32, k0 = blockIdx.y * 32;
    src += (size_t)blockIdx.z * K * N;
    dst += (size_t)blockIdx.z * K * N;
    int tx = threadIdx.x & 31, ty = threadIdx.x >> 5;   // 32 x 8
#pragma unroll
    for (int i = ty; i < 32; i += 8)
        t[i][tx] = f2tf(src[(size_t)(k0 + i) * N + n0 + tx]);
    __syncthreads();
    int pk = ((tx & 3) << 3) | (tx >> 2);               // permuted k within block
#pragma unroll
    for (int i = ty; i < 32; i += 8)
        dst[(size_t)(n0 + i) * K + k0 + pk] = t[tx][i];
}

// ---------------- LayerNorm (emits tf32-rounded, k-permuted values) --------
__global__ void __launch_bounds__(256) ln_kernel(
    const float* __restrict__ x, const float* __restrict__ s,
    const float* __restrict__ b, float* __restrict__ o)
{
    __shared__ float red[2][8];
    int row = blockIdx.x;
    const float* xr = x + (size_t)row * D_;
    float* orow = o + (size_t)row * D_;
    int t = threadIdx.x;
    float v[4];
    float sum = 0.f, sq = 0.f;
#pragma unroll
    for (int i = 0; i < 4; i++) {
        float z = xr[t + i * 256];
        v[i] = z; sum += z; sq += z * z;
    }
#pragma unroll
    for (int off = 16; off > 0; off >>= 1) {
        sum += __shfl_xor_sync(0xffffffffu, sum, off);
        sq  += __shfl_xor_sync(0xffffffffu, sq,  off);
    }
    if ((t & 31) == 0) { red[0][t >> 5] = sum; red[1][t >> 5] = sq; }
    __syncthreads();
    sum = 0.f; sq = 0.f;
#pragma unroll
    for (int i = 0; i < 8; i++) { sum += red[0][i]; sq += red[1][i]; }
    float mean = sum * (1.f / D_);
    float var  = sq  * (1.f / D_) - mean * mean;
    float rstd = rsqrtf(var + 1e-5f);
#pragma unroll
    for (int i = 0; i < 4; i++) {
        int c = t + i * 256;
        orow[permc(c)] = f2tf((v[i] - mean) * rstd * s[c] + b[c]);
    }
}

// ---------------- fragment-packed tf32 GEMM ---------------------------------
// A: [M][Kperm] tf32-rounded. Wt: [N][Kperm] tf32-rounded.
// C(MxN) = A * Wt^T. BM=128, BK=32, 256 thr. Smem rows = 128B, chunk-XOR swizzle.
// EPI bit0:+bias bit1:gelu bit2:+res. ROUND: tf32-round out. PERM: permute out cols.
template<int BN, int WM, int WN, int EPI, int ROUND, int PERM>
__global__ void __launch_bounds__(256, 1) gemm_fr(
    const float* __restrict__ A, const float* __restrict__ Wt,
    const float* __restrict__ bias, const float* __restrict__ res,
    float* __restrict__ C, int M, int N, int K)
{
    const int MI = WM / 16, NI = WN / 8, R8 = MI * 2;
    const int WN_CNT = BN / WN;
    const int A_BYTES = 128 * 128;
    const int B_BYTES = BN * 128;

    extern __shared__ char sm[];
    char* Asm = sm;
    char* Bsm = sm + 3 * A_BYTES;

    int tid = threadIdx.x;
    int bx = blockIdx.x, by = blockIdx.y;
    int wid = tid >> 5, lane = tid & 31;
    int wn = wid % WN_CNT, wm = wid / WN_CNT;
    int g = lane >> 2, q = lane & 3;

    const float* Ab = A  + (size_t)by * 128 * K;
    const float* Bb = Wt + (size_t)bx * BN  * K;
    int KT = K / 32;

    float acc[MI][NI][4];
#pragma unroll
    for (int mi = 0; mi < MI; mi++)
#pragma unroll
        for (int ni = 0; ni < NI; ni++)
#pragma unroll
            for (int k = 0; k < 4; k++) acc[mi][ni][k] = 0.f;

    auto load_tile = [&](int kt, int s) {
#pragma unroll
        for (int i = 0; i < 4; i++) {                 // A: 1024 chunks
            int idx = tid + i * 256;
            int r = idx >> 3, c = idx & 7;
            cp16(Asm + s * A_BYTES + r * 128 + ((c ^ (r & 7)) << 4),
                 Ab + (size_t)r * K + kt * 32 + c * 4);
        }
#pragma unroll
        for (int i = 0; i < BN / 32; i++) {           // B: BN*8 chunks
            int idx = tid + i * 256;
            int r = idx >> 3, c = idx & 7;
            cp16(Bsm + s * B_BYTES + r * 128 + ((c ^ (r & 7)) << 4),
                 Bb + (size_t)r * K + kt * 32 + c * 4);
        }
        cp_commit();
    };

    load_tile(0, 0);
    load_tile(1, 1);

    for (int kt = 0; kt < KT; kt++) {
        asm volatile("cp.async.wait_group 1;");
        __syncthreads();
        if (kt + 2 < KT) load_tile(kt + 2, (kt + 2) % 3);
        else cp_commit();
        int s = kt % 3;
        const char* As = Asm + s * A_BYTES;
        const char* Bs = Bsm + s * B_BYTES;
#pragma unroll
        for (int h2 = 0; h2 < 2; h2++) {
            int ch = ((2 * q + h2) ^ g) << 4;
            float4 ar[R8], br[NI];
#pragma unroll
            for (int rr = 0; rr < R8; rr++) {
                int row = wm * WM + (rr >> 1) * 16 + (rr & 1) * 8 + g;
                ar[rr] = *(const float4*)(As + row * 128 + ch);
            }
#pragma unroll
            for (int ni = 0; ni < NI; ni++) {
                int n = wn * WN + ni * 8 + g;
                br[ni] = *(const float4*)(Bs + n * 128 + ch);
            }
#pragma unroll
            for (int kl = 0; kl < 2; kl++) {
#pragma unroll
                for (int mi = 0; mi < MI; mi++) {
                    const float* a0 = (const float*)&ar[2 * mi];
                    const float* a1 = (const float*)&ar[2 * mi + 1];
                    float a[4] = { a0[kl * 2], a1[kl * 2],
                                   a0[kl * 2 + 1], a1[kl * 2 + 1] };
#pragma unroll
                    for (int ni = 0; ni < NI; ni++) {
                        const float* bp = (const float*)&br[ni];
                        float b2[2] = { bp[kl * 2], bp[kl * 2 + 1] };
                        mma8(acc[mi][ni], a, b2);
                    }
                }
            }
        }
    }

#pragma unroll
    for (int mi = 0; mi < MI; mi++) {
        int r0 = by * 128 + wm * WM + mi * 16 + g;
#pragma unroll
        for (int ni = 0; ni < NI; ni++) {
            int c = bx * BN + wn * WN + ni * 8 + q * 2;
            float2 v0 = make_float2(acc[mi][ni][0], acc[mi][ni][1]);
            float2 v1 = make_float2(acc[mi][ni][2], acc[mi][ni][3]);
            if (EPI & 1) {
                float b0 = bias[c], b1 = bias[c + 1];
                v0.x += b0; v0.y += b1; v1.x += b0; v1.y += b1;
            }
            if (EPI & 2) {
                const float is2 = 0.70710678118654752f;
                v0.x = 0.5f * v0.x * (1.f + erff(v0.x * is2));
                v0.y = 0.5f * v0.y * (1.f + erff(v0.y * is2));
                v1.x = 0.5f * v1.x * (1.f + erff(v1.x * is2));
                v1.y = 0.5f * v1.y * (1.f + erff(v1.y * is2));
            }
            if (EPI & 4) {
                size_t a0 = (size_t)r0 * N + c;
                size_t a1 = (size_t)(r0 + 8) * N + c;
                float2 r0v = *(const float2*)(res + a0);
                float2 r1v = *(const float2*)(res + a1);
                v0.x += r0v.x; v0.y += r0v.y; v1.x += r1v.x; v1.y += r1v.y;
            }
            if (ROUND) {
                v0.x = f2tf(v0.x); v0.y = f2tf(v0.y);
                v1.x = f2tf(v1.x); v1.y = f2tf(v1.y);
            }
            if (PERM) {
                int p0 = permc(c), p1 = permc(c + 1);
                C[(size_t)r0 * N + p0] = v0.x;
                C[(size_t)r0 * N + p1] = v0.y;
                C[(size_t)(r0 + 8) * N + p0] = v1.x;
                C[(size_t)(r0 + 8) * N + p1] = v1.y;
            } else {
                *(float2*)(C + (size_t)r0 * N + c) = v0;
                *(float2*)(C + (size_t)(r0 + 8) * N + c) = v1;
            }
        }
    }
}

// ---------------- attention scores: S = Q K^T * scale (tf32 mma.sync) ------
__global__ void __launch_bounds__(256) scores_tc(
    const float* __restrict__ qkv, float* __restrict__ attn)
{
    __shared__ float Qs[128][36];
    __shared__ float Ks[128][36];
    int bh = blockIdx.z;
    int b = bh >> 4, h = bh & 15;
    int i0 = blockIdx.y * 128, j0 = blockIdx.x * 128;
    const float* Qb = qkv + (size_t)b * N_ * 3 * D_ + (size_t)h * DH_;
    const float* Kb = Qb + D_;
    int tid = threadIdx.x;
    int w = tid >> 5, lane = tid & 31;
    int wm = w >> 1, wn = w & 1;
    int g = lane >> 2, q = lane & 3;

    float acc[2][8][4];
#pragma unroll
    for (int mi = 0; mi < 2; mi++)
#pragma unroll
        for (int ni = 0; ni < 8; ni++)
#pragma unroll
            for (int k = 0; k < 4; k++) acc[mi][ni][k] = 0.f;

#pragma unroll
    for (int k0 = 0; k0 < 64; k0 += 32) {
#pragma unroll
        for (int i = 0; i < 4; i++) {
            int idx = tid + i * 256;
            int r = idx >> 3, c4 = (idx & 7) * 4;
            float4 fq = *(const float4*)(Qb + (size_t)(i0 + r) * 3 * D_ + k0 + c4);
            fq.x = f2tf(fq.x); fq.y = f2tf(fq.y); fq.z = f2tf(fq.z); fq.w = f2tf(fq.w);
            *(float4*)&Qs[r][c4] = fq;
            float4 fk = *(const float4*)(Kb + (size_t)(j0 + r) * 3 * D_ + k0 + c4);
            fk.x = f2tf(fk.x); fk.y = f2tf(fk.y); fk.z = f2tf(fk.z); fk.w = f2tf(fk.w);
            *(float4*)&Ks[r][c4] = fk;
        }
        __syncthreads();
#pragma unroll
        for (int ks = 0; ks < 4; ks++) {
            int kb = ks * 8;
            float a[2][4];
#pragma unroll
            for (int mi = 0; mi < 2; mi++) {
                int m = wm * 32 + mi * 16;
                a[mi][0] = Qs[m + g    ][kb + q];
                a[mi][1] = Qs[m + g + 8][kb + q];
                a[mi][2] = Qs[m + g    ][kb + q + 4];
                a[mi][3] = Qs[m + g + 8][kb + q + 4];
            }
            float bf[8][2];
#pragma unroll
            for (int ni = 0; ni < 8; ni++) {
                int n = wn * 64 + ni * 8 + g;
                bf[ni][0] = Ks[n][kb + q];
                bf[ni][1] = Ks[n][kb + q + 4];
            }
#pragma unroll
            for (int mi = 0; mi < 2; mi++)
#pragma unroll
                for (int ni = 0; ni < 8; ni++) mma8(acc[mi][ni], a[mi], bf[ni]);
        }
        __syncthreads();
    }

    const float scale = 0.03125f;
#pragma unroll
    for (int mi = 0; mi < 2; mi++) {
        int r0 = i0 + wm * 32 + mi * 16 + g;
#pragma unroll
        for (int ni = 0; ni < 8; ni++) {
            int c = j0 + wn * 64 + ni * 8 + q * 2;
            size_t a0 = ((size_t)bh * N_ + r0) * N_ + c;
            size_t a1 = ((size_t)bh * N_ + r0 + 8) * N_ + c;
            *(float2*)(attn + a0) =
                make_float2(acc[mi][ni][0] * scale, acc[mi][ni][1] * scale);
            *(float2*)(attn + a1) =
                make_float2(acc[mi][ni][2] * scale, acc[mi][ni][3] * scale);
        }
    }
}

// ---------------- row softmax over N=1024 ----------------------------------
__global__ void __launch_bounds__(256) softmax_kernel(float* __restrict__ attn)
{
    __shared__ float red[8];
    size_t row = blockIdx.x;
    float* p = attn + row * N_;
    int t = threadIdx.x;
    float v[4];
    float mx = -1e30f;
#pragma unroll
    for (int i = 0; i < 4; i++) { v[i] = p[t + i * 256]; mx = fmaxf(mx, v[i]); }
#pragma unroll
    for (int off = 16; off > 0; off >>= 1)
        mx = fmaxf(mx, __shfl_xor_sync(0xffffffffu, mx, off));
    if ((t & 31) == 0) red[t >> 5] = mx;
    __syncthreads();
    mx = red[0];
#pragma unroll
    for (int i = 1; i < 8; i++) mx = fmaxf(mx, red[i]);
    __syncthreads();
    float sum = 0.f;
#pragma unroll
    for (int i = 0; i < 4; i++) { v[i] = __expf(v[i] - mx); sum += v[i]; }
#pragma unroll
    for (int off = 16; off > 0; off >>= 1)
        sum += __shfl_xor_sync(0xffffffffu, sum, off);
    if ((t & 31) == 0) red[t >> 5] = sum;
    __syncthreads();
    sum = 0.f;
#pragma unroll
    for (int i = 0; i < 8; i++) sum += red[i];
    float inv = 1.f / sum;
#pragma unroll
    for (int i = 0; i < 4; i++) p[t + i * 256] = v[i] * inv;
}

// ---------------- O = attn @ V -> permuted + rounded (GEMM A operand) -------
__global__ void __launch_bounds__(256) av_tc(
    const float* __restrict__ attn, const float* __restrict__ qkv,
    float* __restrict__ o)
{
    __shared__ float As_[128][36];
    __shared__ float Vs[32][68];
    int bh = blockIdx.y;
    int b = bh >> 4, h = bh & 15;
    int i0 = blockIdx.x * 128;
    const float* Ab = attn + ((size_t)bh * N_ + i0) * N_;
    const float* Vb = qkv + (size_t)b * N_ * 3 * D_ + 2 * D_ + (size_t)h * DH_;
    int tid = threadIdx.x;
    int w = tid >> 5, lane = tid & 31;
    int wm = w >> 1, wn = w & 1;
    int g = lane >> 2, q = lane & 3;

    float acc[2][4][4];
#pragma unroll
    for (int mi = 0; mi < 2; mi++)
#pragma unroll
        for (int ni = 0; ni < 4; ni++)
#pragma unroll
            for (int k = 0; k < 4; k++) acc[mi][ni][k] = 0.f;

    for (int k0 = 0; k0 < N_; k0 += 32) {
#pragma unroll
        for (int i = 0; i < 4; i++) {
            int idx = tid + i * 256;
            int r = idx >> 3, c4 = (idx & 7) * 4;
            float4 f = *(const float4*)(Ab + (size_t)r * N_ + k0 + c4);
            f.x = f2tf(f.x); f.y = f2tf(f.y); f.z = f2tf(f.z); f.w = f2tf(f.w);
            *(float4*)&As_[r][c4] = f;
        }
#pragma unroll
        for (int i = 0; i < 2; i++) {
            int idx = tid + i * 256;
            int r = idx >> 4, c4 = (idx & 15) * 4;
            float4 f = *(const float4*)(Vb + (size_t)(k0 + r) * 3 * D_ + c4);
            f.x = f2tf(f.x); f.y = f2tf(f.y); f.z = f2tf(f.z); f.w = f2tf(f.w);
            *(float4*)&Vs[r][c4] = f;
        }
        __syncthreads();
#pragma unroll
        for (int ks = 0; ks < 4; ks++) {
            int kb = ks * 8;
            float a[2][4];
#pragma unroll
            for (int mi = 0; mi < 2; mi++) {
                int m = wm * 32 + mi * 16;
                a[mi][0] = As_[m + g    ][kb + q];
                a[mi][1] = As_[m + g + 8][kb + q];
                a[mi][2] = As_[m + g    ][kb + q + 4];
                a[mi][3] = As_[m + g + 8][kb + q + 4];
            }
            float bf[4][2];
#pragma unroll
            for (int ni = 0; ni < 4; ni++) {
                int n = wn * 32 + ni * 8 + g;
                bf[ni][0] = Vs[kb + q    ][n];
                bf[ni][1] = Vs[kb + q + 4][n];
            }
#pragma unroll
            for (int mi = 0; mi < 2; mi++)
#pragma unroll
                for (int ni = 0; ni < 4; ni++) mma8(acc[mi][ni], a[mi], bf[ni]);
        }
        __syncthreads();
    }

#pragma unroll
    for (int mi = 0; mi < 2; mi++) {
        int r0 = i0 + wm * 32 + mi * 16 + g;
#pragma unroll
        for (int ni = 0; ni < 4; ni++) {
            int cG = h * DH_ + wn * 32 + ni * 8 + q * 2;
            int p0 = permc(cG), p1 = permc(cG + 1);
            size_t b0 = ((size_t)b * N_ + r0) * D_;
            size_t b1 = ((size_t)b * N_ + r0 + 8) * D_;
            o[b0 + p0] = f2tf(acc[mi][ni][0]);
            o[b0 + p1] = f2tf(acc[mi][ni][1]);
            o[b1 + p0] = f2tf(acc[mi][ni][2]);
            o[b1 + p1] = f2tf(acc[mi][ni][3]);
        }
    }
}

// ---------------- orchestration --------------------------------------------
#define FR_SMEM_256 (3 * (128 * 128) + 3 * (256 * 128))   /* 147456 */
#define FR_SMEM_128 (3 * (128 * 128) + 3 * (128 * 128))   /*  98304 */

extern "C" void kernel_launch(void* const* d_in, const int* in_sizes, int n_in,
                              void* d_out, int out_size)
{
    (void)in_sizes; (void)n_in; (void)out_size;
    const float* x     = (const float*)d_in[0];
    const float* ln1_s = (const float*)d_in[1];
    const float* ln1_b = (const float*)d_in[2];
    const float* w_qkv = (const float*)d_in[3];
    const float* w_out = (const float*)d_in[4];
    const float* b_out = (const float*)d_in[5];
    const float* ln2_s = (const float*)d_in[6];
    const float* ln2_b = (const float*)d_in[7];
    const float* w1    = (const float*)d_in[8];
    const float* b1    = (const float*)d_in[9];
    const float* w2    = (const float*)d_in[10];
    const float* b2    = (const float*)d_in[11];
    float* out = (float*)d_out;

    float *h, *qkv, *attn, *o, *mlp, *wqkv, *wout, *w1t, *w2t;
    cudaGetSymbolAddress((void**)&h,    g_h);
    cudaGetSymbolAddress((void**)&qkv,  g_qkv);
    cudaGetSymbolAddress((void**)&attn, g_attn);
    cudaGetSymbolAddress((void**)&o,    g_o);
    cudaGetSymbolAddress((void**)&mlp,  g_mlp);
    cudaGetSymbolAddress((void**)&wqkv, g_wqkv);
    cudaGetSymbolAddress((void**)&wout, g_wout);
    cudaGetSymbolAddress((void**)&w1t,  g_w1);
    cudaGetSymbolAddress((void**)&w2t,  g_w2);

    cudaFuncSetAttribute(gemm_fr<256, 64, 64, 0, 0, 0>,
        cudaFuncAttributeMaxDynamicSharedMemorySize, FR_SMEM_256);
    cudaFuncSetAttribute(gemm_fr<256, 64, 64, 3, 1, 1>,
        cudaFuncAttributeMaxDynamicSharedMemorySize, FR_SMEM_256);
    cudaFuncSetAttribute(gemm_fr<128, 32, 64, 5, 0, 0>,
        cudaFuncAttributeMaxDynamicSharedMemorySize, FR_SMEM_128);

    // pre-pass: weights -> [N][Kperm], tf32-rounded
    wtrans_kernel<<<dim3(3 * D_ / 32, D_ / 32, DEPTH_), 256>>>(w_qkv, wqkv, D_, 3 * D_);
    wtrans_kernel<<<dim3(D_ / 32, D_ / 32, DEPTH_), 256>>>(w_out, wout, D_, D_);
    wtrans_kernel<<<dim3(MLP_ / 32, D_ / 32, DEPTH_), 256>>>(w1, w1t, D_, MLP_);
    wtrans_kernel<<<dim3(D_ / 32, MLP_ / 32, DEPTH_), 256>>>(w2, w2t, MLP_, D_);

    cudaMemcpyAsync(out, x, (size_t)M_ * D_ * sizeof(float),
                    cudaMemcpyDeviceToDevice);

    for (int l = 0; l < DEPTH_; l++) {
        // --- attention block ---
        ln_kernel<<<M_, 256>>>(out, ln1_s + (size_t)l * D_, ln1_b + (size_t)l * D_, h);
        gemm_fr<256, 64, 64, 0, 0, 0><<<dim3(3 * D_ / 256, M_ / 128), 256, FR_SMEM_256>>>(
            h, wqkv + (size_t)l * D_ * 3 * D_, nullptr, nullptr,
            qkv, M_, 3 * D_, D_);
        scores_tc<<<dim3(8, 8, B_ * H_), 256>>>(qkv, attn);
        softmax_kernel<<<B_ * H_ * N_, 256>>>(attn);
        av_tc<<<dim3(8, B_ * H_), 256>>>(attn, qkv, o);
        gemm_fr<128, 32, 64, 5, 0, 0><<<dim3(D_ / 128, M_ / 128), 256, FR_SMEM_128>>>(
            o, wout + (size_t)l * D_ * D_, b_out + (size_t)l * D_,
            out, out, M_, D_, D_);
        // --- MLP block ---
        ln_kernel<<<M_, 256>>>(out, ln2_s + (size_t)l * D_, ln2_b + (size_t)l * D_, h);
        gemm_fr<256, 64, 64, 3, 1, 1><<<dim3(MLP_ / 256, M_ / 128), 256, FR_SMEM_256>>>(
            h, w1t + (size_t)l * D_ * MLP_, b1 + (size_t)l * MLP_,
            nullptr, mlp, M_, MLP_, D_);
        gemm_fr<128, 32, 64, 5, 0, 0><<<dim3(D_ / 128, M_ / 128), 256, FR_SMEM_128>>>(
            mlp, w2t + (size_t)l * MLP_ * D_, b2 + (size_t)l * D_,
            out, out, M_, D_, MLP_);
    }
}

// round 8
// speedup vs baseline: 1.8258x; 1.8258x over previous
#include <cuda_runtime.h>
#include <cuda_fp16.h>
#include <math.h>
#include <stdint.h>

#define B_    2
#define N_    1024
#define D_    1024
#define H_    16
#define DH_   64
#define MLP_  4096
#define DEPTH_ 6
#define M_    (B_ * N_)   /* 2048 rows */

// ---------------- scratch -----------------------------------------------
__device__ __half g_h  [(size_t)M_ * D_];           // LN out (GEMM A, fp16)
__device__ float  g_qkv[(size_t)M_ * 3 * D_];       // natural fp32
__device__ float  g_attn[(size_t)B_ * H_ * N_ * N_];
__device__ __half g_o  [(size_t)M_ * D_];           // attn out (GEMM A, fp16)
__device__ __half g_mlp[(size_t)M_ * MLP_];         // MLP hidden (GEMM A, fp16)
// transposed fp16 weights: [N][K] per layer
__device__ __half g_wqkv[(size_t)DEPTH_ * D_ * 3 * D_];
__device__ __half g_wout[(size_t)DEPTH_ * D_ * D_];
__device__ __half g_w1  [(size_t)DEPTH_ * D_ * MLP_];
__device__ __half g_w2  [(size_t)DEPTH_ * MLP_ * D_];

// ---------------- helpers ---------------------------------------------------
__device__ __forceinline__ float f2tf(float x) {
    uint32_t u; asm("cvt.rna.tf32.f32 %0, %1;" : "=r"(u) : "f"(x));
    return __uint_as_float(u);
}
// tf32 mma (attention kernels)
__device__ __forceinline__ void mma8(float* d, const float* a, const float* b) {
    asm volatile(
        "mma.sync.aligned.m16n8k8.row.col.f32.tf32.tf32.f32 "
        "{%0,%1,%2,%3},{%4,%5,%6,%7},{%8,%9},{%0,%1,%2,%3};"
        : "+f"(d[0]), "+f"(d[1]), "+f"(d[2]), "+f"(d[3])
        : "r"(__float_as_uint(a[0])), "r"(__float_as_uint(a[1])),
          "r"(__float_as_uint(a[2])), "r"(__float_as_uint(a[3])),
          "r"(__float_as_uint(b[0])), "r"(__float_as_uint(b[1])));
}
// fp16 mma with fp32 accum
__device__ __forceinline__ void mma16(float* d, const uint32_t* a, const uint32_t* b) {
    asm volatile(
        "mma.sync.aligned.m16n8k16.row.col.f32.f16.f16.f32 "
        "{%0,%1,%2,%3},{%4,%5,%6,%7},{%8,%9},{%0,%1,%2,%3};"
        : "+f"(d[0]), "+f"(d[1]), "+f"(d[2]), "+f"(d[3])
        : "r"(a[0]), "r"(a[1]), "r"(a[2]), "r"(a[3]),
          "r"(b[0]), "r"(b[1]));
}
__device__ __forceinline__ void cp16(void* smem_dst, const void* gmem_src) {
    uint32_t dst = (uint32_t)__cvta_generic_to_shared(smem_dst);
    asm volatile("cp.async.cg.shared.global [%0], [%1], 16;"
                 :: "r"(dst), "l"(gmem_src));
}
__device__ __forceinline__ void cp_commit() {
    asm volatile("cp.async.commit_group;");
}

// ---------------- weight pre-pass: [K,N] fp32 -> [N,K] fp16 -----------------
__global__ void __launch_bounds__(256) wtrans_kernel(
    const float* __restrict__ src, __half* __restrict__ dst, int K, int N)
{
    __shared__ float t[32][33];
    int n0 = blockIdx.x * 32, k0 = blockIdx.y * 32;
    src += (size_t)blockIdx.z * K * N;
    dst += (size_t)blockIdx.z * K * N;
    int tx = threadIdx.x & 31, ty = threadIdx.x >> 5;   // 32 x 8
#pragma unroll
    for (int i = ty; i < 32; i += 8)
        t[i][tx] = src[(size_t)(k0 + i) * N + n0 + tx];
    __syncthreads();
#pragma unroll
    for (int i = ty; i < 32; i += 8)
        dst[(size_t)(n0 + i) * K + k0 + tx] = __float2half_rn(t[tx][i]);
}

// ---------------- LayerNorm (emits fp16) -----------------------------------
__global__ void __launch_bounds__(256) ln_kernel(
    const float* __restrict__ x, const float* __restrict__ s,
    const float* __restrict__ b, __half* __restrict__ o)
{
    __shared__ float red[2][8];
    int row = blockIdx.x;
    const float* xr = x + (size_t)row * D_;
    __half* orow = o + (size_t)row * D_;
    int t = threadIdx.x;
    float v[4];
    float sum = 0.f, sq = 0.f;
#pragma unroll
    for (int i = 0; i < 4; i++) {
        float z = xr[t + i * 256];
        v[i] = z; sum += z; sq += z * z;
    }
#pragma unroll
    for (int off = 16; off > 0; off >>= 1) {
        sum += __shfl_xor_sync(0xffffffffu, sum, off);
        sq  += __shfl_xor_sync(0xffffffffu, sq,  off);
    }
    if ((t & 31) == 0) { red[0][t >> 5] = sum; red[1][t >> 5] = sq; }
    __syncthreads();
    sum = 0.f; sq = 0.f;
#pragma unroll
    for (int i = 0; i < 8; i++) { sum += red[0][i]; sq += red[1][i]; }
    float mean = sum * (1.f / D_);
    float var  = sq  * (1.f / D_) - mean * mean;
    float rstd = rsqrtf(var + 1e-5f);
#pragma unroll
    for (int i = 0; i < 4; i++) {
        int c = t + i * 256;
        orow[c] = __float2half_rn((v[i] - mean) * rstd * s[c] + b[c]);
    }
}

// ---------------- fp16 tensor-core GEMM, cp.async double-buffered ----------
// A: [M][K] fp16. Wt: [N][K] fp16. C = A*Wt^T (+epilogue).
// BM=128, BK=64 halves (128B rows), 256 thr (8 warps). Warp tile WM x WN.
// Smem rows padded to 72 halves (144B) -> conflict-free fragment loads.
// EPI bit0:+bias bit1:gelu bit2:+res.  OH: write __half output.
template<int BN, int WM, int WN, int EPI, int OH>
__global__ void __launch_bounds__(256, 1) gemm_hf(
    const __half* __restrict__ A, const __half* __restrict__ Wt,
    const float* __restrict__ bias, const float* __restrict__ res,
    void* __restrict__ Cv, int M, int N, int K)
{
    const int MI = WM / 16, NI = WN / 8;
    const int WN_CNT = BN / WN;
    const int RS = 144;                       // row stride bytes (72 halves)
    const int A_BYTES = 128 * RS;
    const int B_BYTES = BN * RS;

    extern __shared__ char sm[];
    char* Asm = sm;
    char* Bsm = sm + 2 * A_BYTES;

    int tid = threadIdx.x;
    int bx = blockIdx.x, by = blockIdx.y;
    int wid = tid >> 5, lane = tid & 31;
    int wn = wid % WN_CNT, wm = wid / WN_CNT;
    int g = lane >> 2, q = lane & 3;

    const __half* Ab = A  + (size_t)by * 128 * K;
    const __half* Bb = Wt + (size_t)bx * BN  * K;
    int KT = K / 64;

    float acc[MI][NI][4];
#pragma unroll
    for (int mi = 0; mi < MI; mi++)
#pragma unroll
        for (int ni = 0; ni < NI; ni++)
#pragma unroll
            for (int k = 0; k < 4; k++) acc[mi][ni][k] = 0.f;

    auto load_tile = [&](int kt, int s) {
#pragma unroll
        for (int i = 0; i < 4; i++) {                 // A: 128 rows x 8 chunks
            int idx = tid + i * 256;
            int r = idx >> 3, c = idx & 7;
            cp16(Asm + s * A_BYTES + r * RS + c * 16,
                 Ab + (size_t)r * K + kt * 64 + c * 8);
        }
#pragma unroll
        for (int i = 0; i < BN / 32; i++) {           // B: BN rows x 8 chunks
            int idx = tid + i * 256;
            int r = idx >> 3, c = idx & 7;
            cp16(Bsm + s * B_BYTES + r * RS + c * 16,
                 Bb + (size_t)r * K + kt * 64 + c * 8);
        }
        cp_commit();
    };

    load_tile(0, 0);

    for (int kt = 0; kt < KT; kt++) {
        int s = kt & 1;
        if (kt + 1 < KT) {
            load_tile(kt + 1, (kt + 1) & 1);
            asm volatile("cp.async.wait_group 1;");
        } else {
            asm volatile("cp.async.wait_group 0;");
        }
        __syncthreads();
        const char* As = Asm + s * A_BYTES;
        const char* Bs = Bsm + s * B_BYTES;
#pragma unroll
        for (int ks = 0; ks < 4; ks++) {
            int kb = ks * 32;                         // 16 halves per step
            uint32_t a[MI][4];
#pragma unroll
            for (int mi = 0; mi < MI; mi++) {
                const char* p0 = As + (wm * WM + mi * 16 + g) * RS + kb + 4 * q;
                const char* p1 = As + (wm * WM + mi * 16 + 8 + g) * RS + kb + 4 * q;
                a[mi][0] = *(const uint32_t*)(p0);
                a[mi][1] = *(const uint32_t*)(p1);
                a[mi][2] = *(const uint32_t*)(p0 + 16);
                a[mi][3] = *(const uint32_t*)(p1 + 16);
            }
            uint32_t b[NI][2];
#pragma unroll
            for (int ni = 0; ni < NI; ni++) {
                const char* pb = Bs + (wn * WN + ni * 8 + g) * RS + kb + 4 * q;
                b[ni][0] = *(const uint32_t*)(pb);
                b[ni][1] = *(const uint32_t*)(pb + 16);
            }
#pragma unroll
            for (int mi = 0; mi < MI; mi++)
#pragma unroll
                for (int ni = 0; ni < NI; ni++) mma16(acc[mi][ni], a[mi], b[ni]);
        }
        __syncthreads();
    }

#pragma unroll
    for (int mi = 0; mi < MI; mi++) {
        int r0 = by * 128 + wm * WM + mi * 16 + g;
#pragma unroll
        for (int ni = 0; ni < NI; ni++) {
            int c = bx * BN + wn * WN + ni * 8 + q * 2;
            float2 v0 = make_float2(acc[mi][ni][0], acc[mi][ni][1]);
            float2 v1 = make_float2(acc[mi][ni][2], acc[mi][ni][3]);
            if (EPI & 1) {
                float b0 = bias[c], b1 = bias[c + 1];
                v0.x += b0; v0.y += b1; v1.x += b0; v1.y += b1;
            }
            if (EPI & 2) {
                const float is2 = 0.70710678118654752f;
                v0.x = 0.5f * v0.x * (1.f + erff(v0.x * is2));
                v0.y = 0.5f * v0.y * (1.f + erff(v0.y * is2));
                v1.x = 0.5f * v1.x * (1.f + erff(v1.x * is2));
                v1.y = 0.5f * v1.y * (1.f + erff(v1.y * is2));
            }
            size_t a0 = (size_t)r0 * N + c;
            size_t a1 = (size_t)(r0 + 8) * N + c;
            if (EPI & 4) {
                float2 r0v = *(const float2*)(res + a0);
                float2 r1v = *(const float2*)(res + a1);
                v0.x += r0v.x; v0.y += r0v.y; v1.x += r1v.x; v1.y += r1v.y;
            }
            if (OH) {
                __half* C = (__half*)Cv;
                *(__half2*)(C + a0) = __floats2half2_rn(v0.x, v0.y);
                *(__half2*)(C + a1) = __floats2half2_rn(v1.x, v1.y);
            } else {
                float* C = (float*)Cv;
                *(float2*)(C + a0) = v0;
                *(float2*)(C + a1) = v1;
            }
        }
    }
}

// ---------------- attention scores: S = Q K^T * scale (tf32 mma.sync) ------
__global__ void __launch_bounds__(256) scores_tc(
    const float* __restrict__ qkv, float* __restrict__ attn)
{
    __shared__ float Qs[128][36];
    __shared__ float Ks[128][36];
    int bh = blockIdx.z;
    int b = bh >> 4, h = bh & 15;
    int i0 = blockIdx.y * 128, j0 = blockIdx.x * 128;
    const float* Qb = qkv + (size_t)b * N_ * 3 * D_ + (size_t)h * DH_;
    const float* Kb = Qb + D_;
    int tid = threadIdx.x;
    int w = tid >> 5, lane = tid & 31;
    int wm = w >> 1, wn = w & 1;
    int g = lane >> 2, q = lane & 3;

    float acc[2][8][4];
#pragma unroll
    for (int mi = 0; mi < 2; mi++)
#pragma unroll
        for (int ni = 0; ni < 8; ni++)
#pragma unroll
            for (int k = 0; k < 4; k++) acc[mi][ni][k] = 0.f;

#pragma unroll
    for (int k0 = 0; k0 < 64; k0 += 32) {
#pragma unroll
        for (int i = 0; i < 4; i++) {
            int idx = tid + i * 256;
            int r = idx >> 3, c4 = (idx & 7) * 4;
            float4 fq = *(const float4*)(Qb + (size_t)(i0 + r) * 3 * D_ + k0 + c4);
            fq.x = f2tf(fq.x); fq.y = f2tf(fq.y); fq.z = f2tf(fq.z); fq.w = f2tf(fq.w);
            *(float4*)&Qs[r][c4] = fq;
            float4 fk = *(const float4*)(Kb + (size_t)(j0 + r) * 3 * D_ + k0 + c4);
            fk.x = f2tf(fk.x); fk.y = f2tf(fk.y); fk.z = f2tf(fk.z); fk.w = f2tf(fk.w);
            *(float4*)&Ks[r][c4] = fk;
        }
        __syncthreads();
#pragma unroll
        for (int ks = 0; ks < 4; ks++) {
            int kb = ks * 8;
            float a[2][4];
#pragma unroll
            for (int mi = 0; mi < 2; mi++) {
                int m = wm * 32 + mi * 16;
                a[mi][0] = Qs[m + g    ][kb + q];
                a[mi][1] = Qs[m + g + 8][kb + q];
                a[mi][2] = Qs[m + g    ][kb + q + 4];
                a[mi][3] = Qs[m + g + 8][kb + q + 4];
            }
            float bf[8][2];
#pragma unroll
            for (int ni = 0; ni < 8; ni++) {
                int n = wn * 64 + ni * 8 + g;
                bf[ni][0] = Ks[n][kb + q];
                bf[ni][1] = Ks[n][kb + q + 4];
            }
#pragma unroll
            for (int mi = 0; mi < 2; mi++)
#pragma unroll
                for (int ni = 0; ni < 8; ni++) mma8(acc[mi][ni], a[mi], bf[ni]);
        }
        __syncthreads();
    }

    const float scale = 0.03125f;
#pragma unroll
    for (int mi = 0; mi < 2; mi++) {
        int r0 = i0 + wm * 32 + mi * 16 + g;
#pragma unroll
        for (int ni = 0; ni < 8; ni++) {
            int c = j0 + wn * 64 + ni * 8 + q * 2;
            size_t a0 = ((size_t)bh * N_ + r0) * N_ + c;
            size_t a1 = ((size_t)bh * N_ + r0 + 8) * N_ + c;
            *(float2*)(attn + a0) =
                make_float2(acc[mi][ni][0] * scale, acc[mi][ni][1] * scale);
            *(float2*)(attn + a1) =
                make_float2(acc[mi][ni][2] * scale, acc[mi][ni][3] * scale);
        }
    }
}

// ---------------- row softmax over N=1024 ----------------------------------
__global__ void __launch_bounds__(256) softmax_kernel(float* __restrict__ attn)
{
    __shared__ float red[8];
    size_t row = blockIdx.x;
    float* p = attn + row * N_;
    int t = threadIdx.x;
    float v[4];
    float mx = -1e30f;
#pragma unroll
    for (int i = 0; i < 4; i++) { v[i] = p[t + i * 256]; mx = fmaxf(mx, v[i]); }
#pragma unroll
    for (int off = 16; off > 0; off >>= 1)
        mx = fmaxf(mx, __shfl_xor_sync(0xffffffffu, mx, off));
    if ((t & 31) == 0) red[t >> 5] = mx;
    __syncthreads();
    mx = red[0];
#pragma unroll
    for (int i = 1; i < 8; i++) mx = fmaxf(mx, red[i]);
    __syncthreads();
    float sum = 0.f;
#pragma unroll
    for (int i = 0; i < 4; i++) { v[i] = __expf(v[i] - mx); sum += v[i]; }
#pragma unroll
    for (int off = 16; off > 0; off >>= 1)
        sum += __shfl_xor_sync(0xffffffffu, sum, off);
    if ((t & 31) == 0) red[t >> 5] = sum;
    __syncthreads();
    sum = 0.f;
#pragma unroll
    for (int i = 0; i < 8; i++) sum += red[i];
    float inv = 1.f / sum;
#pragma unroll
    for (int i = 0; i < 4; i++) p[t + i * 256] = v[i] * inv;
}

// ---------------- O = attn @ V (tf32), output fp16 [b, n, h*dh] -------------
__global__ void __launch_bounds__(256) av_tc(
    const float* __restrict__ attn, const float* __restrict__ qkv,
    __half* __restrict__ o)
{
    __shared__ float As_[128][36];
    __shared__ float Vs[32][68];
    int bh = blockIdx.y;
    int b = bh >> 4, h = bh & 15;
    int i0 = blockIdx.x * 128;
    const float* Ab = attn + ((size_t)bh * N_ + i0) * N_;
    const float* Vb = qkv + (size_t)b * N_ * 3 * D_ + 2 * D_ + (size_t)h * DH_;
    int tid = threadIdx.x;
    int w = tid >> 5, lane = tid & 31;
    int wm = w >> 1, wn = w & 1;
    int g = lane >> 2, q = lane & 3;

    float acc[2][4][4];
#pragma unroll
    for (int mi = 0; mi < 2; mi++)
#pragma unroll
        for (int ni = 0; ni < 4; ni++)
#pragma unroll
            for (int k = 0; k < 4; k++) acc[mi][ni][k] = 0.f;

    for (int k0 = 0; k0 < N_; k0 += 32) {
#pragma unroll
        for (int i = 0; i < 4; i++) {
            int idx = tid + i * 256;
            int r = idx >> 3, c4 = (idx & 7) * 4;
            float4 f = *(const float4*)(Ab + (size_t)r * N_ + k0 + c4);
            f.x = f2tf(f.x); f.y = f2tf(f.y); f.z = f2tf(f.z); f.w = f2tf(f.w);
            *(float4*)&As_[r][c4] = f;
        }
#pragma unroll
        for (int i = 0; i < 2; i++) {
            int idx = tid + i * 256;
            int r = idx >> 4, c4 = (idx & 15) * 4;
            float4 f = *(const float4*)(Vb + (size_t)(k0 + r) * 3 * D_ + c4);
            f.x = f2tf(f.x); f.y = f2tf(f.y); f.z = f2tf(f.z); f.w = f2tf(f.w);
            *(float4*)&Vs[r][c4] = f;
        }
        __syncthreads();
#pragma unroll
        for (int ks = 0; ks < 4; ks++) {
            int kb = ks * 8;
            float a[2][4];
#pragma unroll
            for (int mi = 0; mi < 2; mi++) {
                int m = wm * 32 + mi * 16;
                a[mi][0] = As_[m + g    ][kb + q];
                a[mi][1] = As_[m + g + 8][kb + q];
                a[mi][2] = As_[m + g    ][kb + q + 4];
                a[mi][3] = As_[m + g + 8][kb + q + 4];
            }
            float bf[4][2];
#pragma unroll
            for (int ni = 0; ni < 4; ni++) {
                int n = wn * 32 + ni * 8 + g;
                bf[ni][0] = Vs[kb + q    ][n];
                bf[ni][1] = Vs[kb + q + 4][n];
            }
#pragma unroll
            for (int mi = 0; mi < 2; mi++)
#pragma unroll
                for (int ni = 0; ni < 4; ni++) mma8(acc[mi][ni], a[mi], bf[ni]);
        }
        __syncthreads();
    }

#pragma unroll
    for (int mi = 0; mi < 2; mi++) {
        int r0 = i0 + wm * 32 + mi * 16 + g;
#pragma unroll
        for (int ni = 0; ni < 4; ni++) {
            int c = h * DH_ + wn * 32 + ni * 8 + q * 2;
            size_t a0 = ((size_t)b * N_ + r0) * D_ + c;
            size_t a1 = ((size_t)b * N_ + r0 + 8) * D_ + c;
            *(__half2*)(o + a0) = __floats2half2_rn(acc[mi][ni][0], acc[mi][ni][1]);
            *(__half2*)(o + a1) = __floats2half2_rn(acc[mi][ni][2], acc[mi][ni][3]);
        }
    }
}

// ---------------- orchestration --------------------------------------------
#define HF_SMEM_256 (2 * (128 * 144) + 2 * (256 * 144))   /* 110592 */
#define HF_SMEM_128 (2 * (128 * 144) + 2 * (128 * 144))   /*  73728 */

extern "C" void kernel_launch(void* const* d_in, const int* in_sizes, int n_in,
                              void* d_out, int out_size)
{
    (void)in_sizes; (void)n_in; (void)out_size;
    const float* x     = (const float*)d_in[0];
    const float* ln1_s = (const float*)d_in[1];
    const float* ln1_b = (const float*)d_in[2];
    const float* w_qkv = (const float*)d_in[3];
    const float* w_out = (const float*)d_in[4];
    const float* b_out = (const float*)d_in[5];
    const float* ln2_s = (const float*)d_in[6];
    const float* ln2_b = (const float*)d_in[7];
    const float* w1    = (const float*)d_in[8];
    const float* b1    = (const float*)d_in[9];
    const float* w2    = (const float*)d_in[10];
    const float* b2    = (const float*)d_in[11];
    float* out = (float*)d_out;

    __half *h, *o, *mlp, *wqkv, *wout, *w1t, *w2t;
    float *qkv, *attn;
    cudaGetSymbolAddress((void**)&h,    g_h);
    cudaGetSymbolAddress((void**)&qkv,  g_qkv);
    cudaGetSymbolAddress((void**)&attn, g_attn);
    cudaGetSymbolAddress((void**)&o,    g_o);
    cudaGetSymbolAddress((void**)&mlp,  g_mlp);
    cudaGetSymbolAddress((void**)&wqkv, g_wqkv);
    cudaGetSymbolAddress((void**)&wout, g_wout);
    cudaGetSymbolAddress((void**)&w1t,  g_w1);
    cudaGetSymbolAddress((void**)&w2t,  g_w2);

    cudaFuncSetAttribute(gemm_hf<256, 64, 64, 0, 0>,
        cudaFuncAttributeMaxDynamicSharedMemorySize, HF_SMEM_256);
    cudaFuncSetAttribute(gemm_hf<256, 64, 64, 3, 1>,
        cudaFuncAttributeMaxDynamicSharedMemorySize, HF_SMEM_256);
    cudaFuncSetAttribute(gemm_hf<128, 32, 64, 5, 0>,
        cudaFuncAttributeMaxDynamicSharedMemorySize, HF_SMEM_128);

    // pre-pass: weights -> [N][K] fp16
    wtrans_kernel<<<dim3(3 * D_ / 32, D_ / 32, DEPTH_), 256>>>(w_qkv, wqkv, D_, 3 * D_);
    wtrans_kernel<<<dim3(D_ / 32, D_ / 32, DEPTH_), 256>>>(w_out, wout, D_, D_);
    wtrans_kernel<<<dim3(MLP_ / 32, D_ / 32, DEPTH_), 256>>>(w1, w1t, D_, MLP_);
    wtrans_kernel<<<dim3(D_ / 32, MLP_ / 32, DEPTH_), 256>>>(w2, w2t, MLP_, D_);

    cudaMemcpyAsync(out, x, (size_t)M_ * D_ * sizeof(float),
                    cudaMemcpyDeviceToDevice);

    for (int l = 0; l < DEPTH_; l++) {
        // --- attention block ---
        ln_kernel<<<M_, 256>>>(out, ln1_s + (size_t)l * D_, ln1_b + (size_t)l * D_, h);
        gemm_hf<256, 64, 64, 0, 0><<<dim3(3 * D_ / 256, M_ / 128), 256, HF_SMEM_256>>>(
            h, wqkv + (size_t)l * D_ * 3 * D_, nullptr, nullptr,
            qkv, M_, 3 * D_, D_);
        scores_tc<<<dim3(8, 8, B_ * H_), 256>>>(qkv, attn);
        softmax_kernel<<<B_ * H_ * N_, 256>>>(attn);
        av_tc<<<dim3(8, B_ * H_), 256>>>(attn, qkv, o);
        gemm_hf<128, 32, 64, 5, 0><<<dim3(D_ / 128, M_ / 128), 256, HF_SMEM_128>>>(
            o, wout + (size_t)l * D_ * D_, b_out + (size_t)l * D_,
            out, out, M_, D_, D_);
        // --- MLP block ---
        ln_kernel<<<M_, 256>>>(out, ln2_s + (size_t)l * D_, ln2_b + (size_t)l * D_, h);
        gemm_hf<256, 64, 64, 3, 1><<<dim3(MLP_ / 256, M_ / 128), 256, HF_SMEM_256>>>(
            h, w1t + (size_t)l * D_ * MLP_, b1 + (size_t)l * MLP_,
            nullptr, mlp, M_, MLP_, D_);
        gemm_hf<128, 32, 64, 5, 0><<<dim3(D_ / 128, M_ / 128), 256, HF_SMEM_128>>>(
            mlp, w2t + (size_t)l * MLP_ * D_, b2 + (size_t)l * D_,
            out, out, M_, D_, MLP_);
    }
}

// round 9
// speedup vs baseline: 2.2719x; 1.2443x over previous
#include <cuda_runtime.h>
#include <cuda_fp16.h>
#include <math.h>
#include <stdint.h>

#define B_    2
#define N_    1024
#define D_    1024
#define H_    16
#define DH_   64
#define MLP_  4096
#define DEPTH_ 6
#define M_    (B_ * N_)   /* 2048 rows */

// ---------------- scratch -----------------------------------------------
__device__ __half g_h  [(size_t)M_ * D_];           // LN out (fp16)
__device__ __half g_qkv[(size_t)M_ * 3 * D_];       // QKV out (fp16)
__device__ __half g_attn[(size_t)B_ * H_ * N_ * N_];// attention (fp16, 64MB)
__device__ __half g_vt [(size_t)B_ * H_ * DH_ * N_];// V transposed [bh][d][j]
__device__ __half g_o  [(size_t)M_ * D_];           // attn out (fp16)
__device__ __half g_mlp[(size_t)M_ * MLP_];         // MLP hidden (fp16)
// transposed fp16 weights: [N][K] per layer
__device__ __half g_wqkv[(size_t)DEPTH_ * D_ * 3 * D_];
__device__ __half g_wout[(size_t)DEPTH_ * D_ * D_];
__device__ __half g_w1  [(size_t)DEPTH_ * D_ * MLP_];
__device__ __half g_w2  [(size_t)DEPTH_ * MLP_ * D_];

// ---------------- helpers ---------------------------------------------------
__device__ __forceinline__ void mma16(float* d, const uint32_t* a, const uint32_t* b) {
    asm volatile(
        "mma.sync.aligned.m16n8k16.row.col.f32.f16.f16.f32 "
        "{%0,%1,%2,%3},{%4,%5,%6,%7},{%8,%9},{%0,%1,%2,%3};"
        : "+f"(d[0]), "+f"(d[1]), "+f"(d[2]), "+f"(d[3])
        : "r"(a[0]), "r"(a[1]), "r"(a[2]), "r"(a[3]),
          "r"(b[0]), "r"(b[1]));
}
__device__ __forceinline__ void cp16(void* smem_dst, const void* gmem_src) {
    uint32_t dst = (uint32_t)__cvta_generic_to_shared(smem_dst);
    asm volatile("cp.async.cg.shared.global [%0], [%1], 16;"
                 :: "r"(dst), "l"(gmem_src));
}
__device__ __forceinline__ void cp_commit() {
    asm volatile("cp.async.commit_group;");
}

// ---------------- weight pre-pass: [K,N] fp32 -> [N,K] fp16 -----------------
__global__ void __launch_bounds__(256) wtrans_kernel(
    const float* __restrict__ src, __half* __restrict__ dst, int K, int N)
{
    __shared__ float t[32][33];
    int n0 = blockIdx.x * 32, k0 = blockIdx.y * 32;
    src += (size_t)blockIdx.z * K * N;
    dst += (size_t)blockIdx.z * K * N;
    int tx = threadIdx.x & 31, ty = threadIdx.x >> 5;
#pragma unroll
    for (int i = ty; i < 32; i += 8)
        t[i][tx] = src[(size_t)(k0 + i) * N + n0 + tx];
    __syncthreads();
#pragma unroll
    for (int i = ty; i < 32; i += 8)
        dst[(size_t)(n0 + i) * K + k0 + tx] = __float2half_rn(t[tx][i]);
}

// ---------------- V transpose: qkv fp16 -> Vt[bh][d][j] ---------------------
__global__ void __launch_bounds__(256) vtrans_kernel(
    const __half* __restrict__ qkv, __half* __restrict__ vt)
{
    __shared__ __half t[64][66];
    int bh = blockIdx.y;
    int b = bh >> 4, h = bh & 15;
    int j0 = blockIdx.x * 64;
    const __half* src = qkv + (size_t)b * N_ * 3 * D_ + 2 * D_ + (size_t)h * DH_;
    __half* dst = vt + (size_t)bh * DH_ * N_;
    int tid = threadIdx.x;
#pragma unroll
    for (int i = 0; i < 16; i++) {
        int idx = tid + i * 256;
        int j = idx >> 6, d = idx & 63;
        t[j][d] = src[(size_t)(j0 + j) * 3 * D_ + d];
    }
    __syncthreads();
#pragma unroll
    for (int i = 0; i < 16; i++) {
        int idx = tid + i * 256;
        int d = idx >> 6, j = idx & 63;
        dst[(size_t)d * N_ + j0 + j] = t[j][d];
    }
}

// ---------------- LayerNorm (emits fp16) -----------------------------------
__global__ void __launch_bounds__(256) ln_kernel(
    const float* __restrict__ x, const float* __restrict__ s,
    const float* __restrict__ b, __half* __restrict__ o)
{
    __shared__ float red[2][8];
    int row = blockIdx.x;
    const float* xr = x + (size_t)row * D_;
    __half* orow = o + (size_t)row * D_;
    int t = threadIdx.x;
    float v[4];
    float sum = 0.f, sq = 0.f;
#pragma unroll
    for (int i = 0; i < 4; i++) {
        float z = xr[t + i * 256];
        v[i] = z; sum += z; sq += z * z;
    }
#pragma unroll
    for (int off = 16; off > 0; off >>= 1) {
        sum += __shfl_xor_sync(0xffffffffu, sum, off);
        sq  += __shfl_xor_sync(0xffffffffu, sq,  off);
    }
    if ((t & 31) == 0) { red[0][t >> 5] = sum; red[1][t >> 5] = sq; }
    __syncthreads();
    sum = 0.f; sq = 0.f;
#pragma unroll
    for (int i = 0; i < 8; i++) { sum += red[0][i]; sq += red[1][i]; }
    float mean = sum * (1.f / D_);
    float var  = sq  * (1.f / D_) - mean * mean;
    float rstd = rsqrtf(var + 1e-5f);
#pragma unroll
    for (int i = 0; i < 4; i++) {
        int c = t + i * 256;
        orow[c] = __float2half_rn((v[i] - mean) * rstd * s[c] + b[c]);
    }
}

// ---------------- fp16 tensor-core GEMM, cp.async double-buffered ----------
template<int BN, int WM, int WN, int EPI, int OH>
__global__ void __launch_bounds__(256, 1) gemm_hf(
    const __half* __restrict__ A, const __half* __restrict__ Wt,
    const float* __restrict__ bias, const float* __restrict__ res,
    void* __restrict__ Cv, int M, int N, int K)
{
    const int MI = WM / 16, NI = WN / 8;
    const int WN_CNT = BN / WN;
    const int RS = 144;
    const int A_BYTES = 128 * RS;
    const int B_BYTES = BN * RS;

    extern __shared__ char sm[];
    char* Asm = sm;
    char* Bsm = sm + 2 * A_BYTES;

    int tid = threadIdx.x;
    int bx = blockIdx.x, by = blockIdx.y;
    int wid = tid >> 5, lane = tid & 31;
    int wn = wid % WN_CNT, wm = wid / WN_CNT;
    int g = lane >> 2, q = lane & 3;

    const __half* Ab = A  + (size_t)by * 128 * K;
    const __half* Bb = Wt + (size_t)bx * BN  * K;
    int KT = K / 64;

    float acc[MI][NI][4];
#pragma unroll
    for (int mi = 0; mi < MI; mi++)
#pragma unroll
        for (int ni = 0; ni < NI; ni++)
#pragma unroll
            for (int k = 0; k < 4; k++) acc[mi][ni][k] = 0.f;

    auto load_tile = [&](int kt, int s) {
#pragma unroll
        for (int i = 0; i < 4; i++) {
            int idx = tid + i * 256;
            int r = idx >> 3, c = idx & 7;
            cp16(Asm + s * A_BYTES + r * RS + c * 16,
                 Ab + (size_t)r * K + kt * 64 + c * 8);
        }
#pragma unroll
        for (int i = 0; i < BN / 32; i++) {
            int idx = tid + i * 256;
            int r = idx >> 3, c = idx & 7;
            cp16(Bsm + s * B_BYTES + r * RS + c * 16,
                 Bb + (size_t)r * K + kt * 64 + c * 8);
        }
        cp_commit();
    };

    load_tile(0, 0);

    for (int kt = 0; kt < KT; kt++) {
        int s = kt & 1;
        if (kt + 1 < KT) {
            load_tile(kt + 1, (kt + 1) & 1);
            asm volatile("cp.async.wait_group 1;");
        } else {
            asm volatile("cp.async.wait_group 0;");
        }
        __syncthreads();
        const char* As = Asm + s * A_BYTES;
        const char* Bs = Bsm + s * B_BYTES;
#pragma unroll
        for (int ks = 0; ks < 4; ks++) {
            int kb = ks * 32;
            uint32_t a[MI][4];
#pragma unroll
            for (int mi = 0; mi < MI; mi++) {
                const char* p0 = As + (wm * WM + mi * 16 + g) * RS + kb + 4 * q;
                const char* p1 = As + (wm * WM + mi * 16 + 8 + g) * RS + kb + 4 * q;
                a[mi][0] = *(const uint32_t*)(p0);
                a[mi][1] = *(const uint32_t*)(p1);
                a[mi][2] = *(const uint32_t*)(p0 + 16);
                a[mi][3] = *(const uint32_t*)(p1 + 16);
            }
            uint32_t b[NI][2];
#pragma unroll
            for (int ni = 0; ni < NI; ni++) {
                const char* pb = Bs + (wn * WN + ni * 8 + g) * RS + kb + 4 * q;
                b[ni][0] = *(const uint32_t*)(pb);
                b[ni][1] = *(const uint32_t*)(pb + 16);
            }
#pragma unroll
            for (int mi = 0; mi < MI; mi++)
#pragma unroll
                for (int ni = 0; ni < NI; ni++) mma16(acc[mi][ni], a[mi], b[ni]);
        }
        __syncthreads();
    }

#pragma unroll
    for (int mi = 0; mi < MI; mi++) {
        int r0 = by * 128 + wm * WM + mi * 16 + g;
#pragma unroll
        for (int ni = 0; ni < NI; ni++) {
            int c = bx * BN + wn * WN + ni * 8 + q * 2;
            float2 v0 = make_float2(acc[mi][ni][0], acc[mi][ni][1]);
            float2 v1 = make_float2(acc[mi][ni][2], acc[mi][ni][3]);
            if (EPI & 1) {
                float b0 = bias[c], b1 = bias[c + 1];
                v0.x += b0; v0.y += b1; v1.x += b0; v1.y += b1;
            }
            if (EPI & 2) {
                const float is2 = 0.70710678118654752f;
                v0.x = 0.5f * v0.x * (1.f + erff(v0.x * is2));
                v0.y = 0.5f * v0.y * (1.f + erff(v0.y * is2));
                v1.x = 0.5f * v1.x * (1.f + erff(v1.x * is2));
                v1.y = 0.5f * v1.y * (1.f + erff(v1.y * is2));
            }
            size_t a0 = (size_t)r0 * N + c;
            size_t a1 = (size_t)(r0 + 8) * N + c;
            if (EPI & 4) {
                float2 r0v = *(const float2*)(res + a0);
                float2 r1v = *(const float2*)(res + a1);
                v0.x += r0v.x; v0.y += r0v.y; v1.x += r1v.x; v1.y += r1v.y;
            }
            if (OH) {
                __half* C = (__half*)Cv;
                *(__half2*)(C + a0) = __floats2half2_rn(v0.x, v0.y);
                *(__half2*)(C + a1) = __floats2half2_rn(v1.x, v1.y);
            } else {
                float* C = (float*)Cv;
                *(float2*)(C + a0) = v0;
                *(float2*)(C + a1) = v1;
            }
        }
    }
}

// ---------------- attention scores (fp16 mma): S = Q K^T * scale -----------
// grid (j_tiles 8, i_tiles 8, bh 32). Single K block (dh=64).
__global__ void __launch_bounds__(256, 1) scores_hf(
    const __half* __restrict__ qkv, __half* __restrict__ attn)
{
    const int RS = 144;
    extern __shared__ char sm[];
    char* Qs = sm;
    char* Ks = sm + 128 * RS;

    int bh = blockIdx.z;
    int b = bh >> 4, h = bh & 15;
    int i0 = blockIdx.y * 128, j0 = blockIdx.x * 128;
    const __half* Qb = qkv + (size_t)b * N_ * 3 * D_ + (size_t)h * DH_;
    const __half* Kb = Qb + D_;

    int tid = threadIdx.x;
    int wid = tid >> 5, lane = tid & 31;
    int wm = wid >> 1, wn = wid & 1;      // 4 x 2 -> WM=32, WN=64
    int g = lane >> 2, q = lane & 3;

#pragma unroll
    for (int i = 0; i < 4; i++) {
        int idx = tid + i * 256;
        int r = idx >> 3, c = idx & 7;
        cp16(Qs + r * RS + c * 16, Qb + (size_t)(i0 + r) * 3 * D_ + c * 8);
        cp16(Ks + r * RS + c * 16, Kb + (size_t)(j0 + r) * 3 * D_ + c * 8);
    }
    cp_commit();
    asm volatile("cp.async.wait_group 0;");
    __syncthreads();

    float acc[2][8][4];
#pragma unroll
    for (int mi = 0; mi < 2; mi++)
#pragma unroll
        for (int ni = 0; ni < 8; ni++)
#pragma unroll
            for (int k = 0; k < 4; k++) acc[mi][ni][k] = 0.f;

#pragma unroll
    for (int ks = 0; ks < 4; ks++) {
        int kb = ks * 32;
        uint32_t a[2][4];
#pragma unroll
        for (int mi = 0; mi < 2; mi++) {
            const char* p0 = Qs + (wm * 32 + mi * 16 + g) * RS + kb + 4 * q;
            const char* p1 = Qs + (wm * 32 + mi * 16 + 8 + g) * RS + kb + 4 * q;
            a[mi][0] = *(const uint32_t*)(p0);
            a[mi][1] = *(const uint32_t*)(p1);
            a[mi][2] = *(const uint32_t*)(p0 + 16);
            a[mi][3] = *(const uint32_t*)(p1 + 16);
        }
        uint32_t br[8][2];
#pragma unroll
        for (int ni = 0; ni < 8; ni++) {
            const char* pb = Ks + (wn * 64 + ni * 8 + g) * RS + kb + 4 * q;
            br[ni][0] = *(const uint32_t*)(pb);
            br[ni][1] = *(const uint32_t*)(pb + 16);
        }
#pragma unroll
        for (int mi = 0; mi < 2; mi++)
#pragma unroll
            for (int ni = 0; ni < 8; ni++) mma16(acc[mi][ni], a[mi], br[ni]);
    }

    const float scale = 0.03125f;   // D^-0.5 (full-dim per reference)
    __half* Ao = attn + (size_t)bh * N_ * N_;
#pragma unroll
    for (int mi = 0; mi < 2; mi++) {
        int r0 = i0 + wm * 32 + mi * 16 + g;
#pragma unroll
        for (int ni = 0; ni < 8; ni++) {
            int c = j0 + wn * 64 + ni * 8 + q * 2;
            *(__half2*)(Ao + (size_t)r0 * N_ + c) =
                __floats2half2_rn(acc[mi][ni][0] * scale, acc[mi][ni][1] * scale);
            *(__half2*)(Ao + (size_t)(r0 + 8) * N_ + c) =
                __floats2half2_rn(acc[mi][ni][2] * scale, acc[mi][ni][3] * scale);
        }
    }
}

// ---------------- row softmax over N=1024 (fp16 storage) --------------------
__global__ void __launch_bounds__(256) softmax_hf(__half* __restrict__ attn)
{
    __shared__ float red[8];
    size_t row = blockIdx.x;
    __half* p = attn + row * N_;
    int t = threadIdx.x;
    float v[4];
    float mx = -1e30f;
#pragma unroll
    for (int i = 0; i < 4; i++) {
        v[i] = __half2float(p[t + i * 256]);
        mx = fmaxf(mx, v[i]);
    }
#pragma unroll
    for (int off = 16; off > 0; off >>= 1)
        mx = fmaxf(mx, __shfl_xor_sync(0xffffffffu, mx, off));
    if ((t & 31) == 0) red[t >> 5] = mx;
    __syncthreads();
    mx = red[0];
#pragma unroll
    for (int i = 1; i < 8; i++) mx = fmaxf(mx, red[i]);
    __syncthreads();
    float sum = 0.f;
#pragma unroll
    for (int i = 0; i < 4; i++) { v[i] = __expf(v[i] - mx); sum += v[i]; }
#pragma unroll
    for (int off = 16; off > 0; off >>= 1)
        sum += __shfl_xor_sync(0xffffffffu, sum, off);
    if ((t & 31) == 0) red[t >> 5] = sum;
    __syncthreads();
    sum = 0.f;
#pragma unroll
    for (int i = 0; i < 8; i++) sum += red[i];
    float inv = 1.f / sum;
#pragma unroll
    for (int i = 0; i < 4; i++) p[t + i * 256] = __float2half_rn(v[i] * inv);
}

// ---------------- O = attn @ Vt^T (fp16 mma), output fp16 -------------------
// grid (i_tiles 16, bh 32). A=attn [i][j], B=Vt [d][j]. K=1024.
__global__ void __launch_bounds__(256, 1) av_hf(
    const __half* __restrict__ attn, const __half* __restrict__ vt,
    __half* __restrict__ o)
{
    const int RS = 144;
    const int A_BYTES = 128 * RS;
    const int B_BYTES = 64 * RS;
    extern __shared__ char sm[];
    char* Asm = sm;
    char* Bsm = sm + 2 * A_BYTES;

    int bh = blockIdx.y;
    int b = bh >> 4, h = bh & 15;
    int i0 = blockIdx.x * 128;
    const __half* Ab = attn + (size_t)bh * N_ * N_ + (size_t)i0 * N_;
    const __half* Bb = vt + (size_t)bh * DH_ * N_;

    int tid = threadIdx.x;
    int wid = tid >> 5, lane = tid & 31;
    int wm = wid >> 1, wn = wid & 1;      // 4 x 2 -> WM=32, WN=32
    int g = lane >> 2, q = lane & 3;

    float acc[2][4][4];
#pragma unroll
    for (int mi = 0; mi < 2; mi++)
#pragma unroll
        for (int ni = 0; ni < 4; ni++)
#pragma unroll
            for (int k = 0; k < 4; k++) acc[mi][ni][k] = 0.f;

    auto load_tile = [&](int kt, int s) {
#pragma unroll
        for (int i = 0; i < 4; i++) {                 // attn: 128 rows x 8 chunks
            int idx = tid + i * 256;
            int r = idx >> 3, c = idx & 7;
            cp16(Asm + s * A_BYTES + r * RS + c * 16,
                 Ab + (size_t)r * N_ + kt * 64 + c * 8);
        }
#pragma unroll
        for (int i = 0; i < 2; i++) {                 // Vt: 64 rows x 8 chunks
            int idx = tid + i * 256;
            int r = idx >> 3, c = idx & 7;
            cp16(Bsm + s * B_BYTES + r * RS + c * 16,
                 Bb + (size_t)r * N_ + kt * 64 + c * 8);
        }
        cp_commit();
    };

    load_tile(0, 0);

    for (int kt = 0; kt < 16; kt++) {
        int s = kt & 1;
        if (kt + 1 < 16) {
            load_tile(kt + 1, (kt + 1) & 1);
            asm volatile("cp.async.wait_group 1;");
        } else {
            asm volatile("cp.async.wait_group 0;");
        }
        __syncthreads();
        const char* As = Asm + s * A_BYTES;
        const char* Bs = Bsm + s * B_BYTES;
#pragma unroll
        for (int ks = 0; ks < 4; ks++) {
            int kb = ks * 32;
            uint32_t a[2][4];
#pragma unroll
            for (int mi = 0; mi < 2; mi++) {
                const char* p0 = As + (wm * 32 + mi * 16 + g) * RS + kb + 4 * q;
                const char* p1 = As + (wm * 32 + mi * 16 + 8 + g) * RS + kb + 4 * q;
                a[mi][0] = *(const uint32_t*)(p0);
                a[mi][1] = *(const uint32_t*)(p1);
                a[mi][2] = *(const uint32_t*)(p0 + 16);
                a[mi][3] = *(const uint32_t*)(p1 + 16);
            }
            uint32_t br[4][2];
#pragma unroll
            for (int ni = 0; ni < 4; ni++) {
                const char* pb = Bs + (wn * 32 + ni * 8 + g) * RS + kb + 4 * q;
                br[ni][0] = *(const uint32_t*)(pb);
                br[ni][1] = *(const uint32_t*)(pb + 16);
            }
#pragma unroll
            for (int mi = 0; mi < 2; mi++)
#pragma unroll
                for (int ni = 0; ni < 4; ni++) mma16(acc[mi][ni], a[mi], br[ni]);
        }
        __syncthreads();
    }

#pragma unroll
    for (int mi = 0; mi < 2; mi++) {
        int r0 = i0 + wm * 32 + mi * 16 + g;
#pragma unroll
        for (int ni = 0; ni < 4; ni++) {
            int c = h * DH_ + wn * 32 + ni * 8 + q * 2;
            size_t a0 = ((size_t)b * N_ + r0) * D_ + c;
            size_t a1 = ((size_t)b * N_ + r0 + 8) * D_ + c;
            *(__half2*)(o + a0) = __floats2half2_rn(acc[mi][ni][0], acc[mi][ni][1]);
            *(__half2*)(o + a1) = __floats2half2_rn(acc[mi][ni][2], acc[mi][ni][3]);
        }
    }
}

// ---------------- orchestration --------------------------------------------
#define HF_SMEM_256 (2 * (128 * 144) + 2 * (256 * 144))   /* 110592 */
#define HF_SMEM_128 (2 * (128 * 144) + 2 * (128 * 144))   /*  73728 */
#define SC_SMEM     (2 * (128 * 144))                     /*  36864 */
#define AV_SMEM     (2 * (128 * 144) + 2 * (64 * 144))    /*  55296 */

extern "C" void kernel_launch(void* const* d_in, const int* in_sizes, int n_in,
                              void* d_out, int out_size)
{
    (void)in_sizes; (void)n_in; (void)out_size;
    const float* x     = (const float*)d_in[0];
    const float* ln1_s = (const float*)d_in[1];
    const float* ln1_b = (const float*)d_in[2];
    const float* w_qkv = (const float*)d_in[3];
    const float* w_out = (const float*)d_in[4];
    const float* b_out = (const float*)d_in[5];
    const float* ln2_s = (const float*)d_in[6];
    const float* ln2_b = (const float*)d_in[7];
    const float* w1    = (const float*)d_in[8];
    const float* b1    = (const float*)d_in[9];
    const float* w2    = (const float*)d_in[10];
    const float* b2    = (const float*)d_in[11];
    float* out = (float*)d_out;

    __half *h, *qkv, *attn, *vt, *o, *mlp, *wqkv, *wout, *w1t, *w2t;
    cudaGetSymbolAddress((void**)&h,    g_h);
    cudaGetSymbolAddress((void**)&qkv,  g_qkv);
    cudaGetSymbolAddress((void**)&attn, g_attn);
    cudaGetSymbolAddress((void**)&vt,   g_vt);
    cudaGetSymbolAddress((void**)&o,    g_o);
    cudaGetSymbolAddress((void**)&mlp,  g_mlp);
    cudaGetSymbolAddress((void**)&wqkv, g_wqkv);
    cudaGetSymbolAddress((void**)&wout, g_wout);
    cudaGetSymbolAddress((void**)&w1t,  g_w1);
    cudaGetSymbolAddress((void**)&w2t,  g_w2);

    cudaFuncSetAttribute(gemm_hf<256, 64, 64, 0, 1>,
        cudaFuncAttributeMaxDynamicSharedMemorySize, HF_SMEM_256);
    cudaFuncSetAttribute(gemm_hf<256, 64, 64, 3, 1>,
        cudaFuncAttributeMaxDynamicSharedMemorySize, HF_SMEM_256);
    cudaFuncSetAttribute(gemm_hf<128, 32, 64, 5, 0>,
        cudaFuncAttributeMaxDynamicSharedMemorySize, HF_SMEM_128);
    cudaFuncSetAttribute(scores_hf,
        cudaFuncAttributeMaxDynamicSharedMemorySize, SC_SMEM);
    cudaFuncSetAttribute(av_hf,
        cudaFuncAttributeMaxDynamicSharedMemorySize, AV_SMEM);

    // pre-pass: weights -> [N][K] fp16
    wtrans_kernel<<<dim3(3 * D_ / 32, D_ / 32, DEPTH_), 256>>>(w_qkv, wqkv, D_, 3 * D_);
    wtrans_kernel<<<dim3(D_ / 32, D_ / 32, DEPTH_), 256>>>(w_out, wout, D_, D_);
    wtrans_kernel<<<dim3(MLP_ / 32, D_ / 32, DEPTH_), 256>>>(w1, w1t, D_, MLP_);
    wtrans_kernel<<<dim3(D_ / 32, MLP_ / 32, DEPTH_), 256>>>(w2, w2t, MLP_, D_);

    cudaMemcpyAsync(out, x, (size_t)M_ * D_ * sizeof(float),
                    cudaMemcpyDeviceToDevice);

    for (int l = 0; l < DEPTH_; l++) {
        // --- attention block ---
        ln_kernel<<<M_, 256>>>(out, ln1_s + (size_t)l * D_, ln1_b + (size_t)l * D_, h);
        gemm_hf<256, 64, 64, 0, 1><<<dim3(3 * D_ / 256, M_ / 128), 256, HF_SMEM_256>>>(
            h, wqkv + (size_t)l * D_ * 3 * D_, nullptr, nullptr,
            qkv, M_, 3 * D_, D_);
        vtrans_kernel<<<dim3(N_ / 64, B_ * H_), 256>>>(qkv, vt);
        scores_hf<<<dim3(8, 8, B_ * H_), 256, SC_SMEM>>>(qkv, attn);
        softmax_hf<<<B_ * H_ * N_, 256>>>(attn);
        av_hf<<<dim3(N_ / 128, B_ * H_), 256, AV_SMEM>>>(attn, vt, o);
        gemm_hf<128, 32, 64, 5, 0><<<dim3(D_ / 128, M_ / 128), 256, HF_SMEM_128>>>(
            o, wout + (size_t)l * D_ * D_, b_out + (size_t)l * D_,
            out, out, M_, D_, D_);
        // --- MLP block ---
        ln_kernel<<<M_, 256>>>(out, ln2_s + (size_t)l * D_, ln2_b + (size_t)l * D_, h);
        gemm_hf<256, 64, 64, 3, 1><<<dim3(MLP_ / 256, M_ / 128), 256, HF_SMEM_256>>>(
            h, w1t + (size_t)l * D_ * MLP_, b1 + (size_t)l * MLP_,
            nullptr, mlp, M_, MLP_, D_);
        gemm_hf<128, 32, 64, 5, 0><<<dim3(D_ / 128, M_ / 128), 256, HF_SMEM_128>>>(
            mlp, w2t + (size_t)l * MLP_ * D_, b2 + (size_t)l * D_,
            out, out, M_, D_, MLP_);
    }
}